// round 7
// baseline (speedup 1.0000x reference)
#include <cuda_runtime.h>
#include <cstdint>

#define BB 8
#define NN 1024
#define DD 64
#define HH 32

// Newton h's: odd h in [1,29] (15). MUFU h's: even h + {31} (17).
#define IS_NEWTON(h) (((h) & 1) && (h) < 30)

// Scratch (allocation-free rule -> device globals).
// MUFU h's: raw projection; Newton h's: tanh(projection).
__device__ float g_ca[BB * NN * HH];
__device__ float g_dv[BB * NN * HH];

using u64 = unsigned long long;

__device__ __forceinline__ u64 f2_add(u64 a, u64 b) {
    u64 r; asm("add.rn.f32x2 %0,%1,%2;" : "=l"(r) : "l"(a), "l"(b)); return r;
}
__device__ __forceinline__ u64 f2_mul(u64 a, u64 b) {
    u64 r; asm("mul.rn.f32x2 %0,%1,%2;" : "=l"(r) : "l"(a), "l"(b)); return r;
}
__device__ __forceinline__ u64 f2_fma(u64 a, u64 b, u64 c) {
    u64 r; asm("fma.rn.f32x2 %0,%1,%2,%3;" : "=l"(r) : "l"(a), "l"(b), "l"(c)); return r;
}
__device__ __forceinline__ u64 pack2(float lo, float hi) {
    u64 r; asm("mov.b64 %0,{%1,%2};" : "=l"(r) : "f"(lo), "f"(hi)); return r;
}
__device__ __forceinline__ void unpack2(u64 v, float& lo, float& hi) {
    asm("mov.b64 {%0,%1},%2;" : "=f"(lo), "=f"(hi) : "l"(v));
}
__device__ __forceinline__ float tanh_a(float x) {
    float r; asm("tanh.approx.f32 %0,%1;" : "=f"(r) : "f"(x)); return r;
}
__device__ __forceinline__ float rcp_seed(float d) {   // ~ -1/d
    return __uint_as_float(0xFEF311C3u - __float_as_uint(d));
}

#define ONE2 0x3F8000003F800000ULL

// ---------------------------------------------------------------------------
// Projection: one warp per row, lane = h. MUFU-h raw, Newton-h tanh'd.
// Two independent accumulator chains (halved FFMA dependency depth).
// ---------------------------------------------------------------------------
__global__ __launch_bounds__(128) void proj_kernel(
    const float* __restrict__ cell, const float* __restrict__ drug,
    const float* __restrict__ w_q, const float* __restrict__ w_k,
    const float* __restrict__ bias)
{
    int warp = threadIdx.x >> 5;
    int lane = threadIdx.x & 31;
    int row  = blockIdx.x * 4 + warp;          // 0 .. 2*B*N-1
    bool is_drug = row >= BB * NN;
    int r = is_drug ? row - BB * NN : row;
    const float* src = (is_drug ? drug : cell) + r * DD;
    const float* W   = is_drug ? w_q : w_k;    // [D][H] row-major

    float x0 = src[lane];
    float x1 = src[lane + 32];

    float acc0 = is_drug ? bias[lane] : 0.0f;
    float acc1 = 0.0f;
#pragma unroll
    for (int d = 0; d < 32; d++) {
        float rd = __shfl_sync(0xFFFFFFFFu, x0, d);
        acc0 = fmaf(rd, W[d * HH + lane], acc0);
        float rd1 = __shfl_sync(0xFFFFFFFFu, x1, d);
        acc1 = fmaf(rd1, W[(d + 32) * HH + lane], acc1);
    }
    float acc = acc0 + acc1;
    if (IS_NEWTON(lane)) acc = tanh_a(acc);    // Newton lanes store tanh'd value
    (is_drug ? g_dv : g_ca)[r * HH + lane] = acc;
}

// ---------------------------------------------------------------------------
// Co-attention: 64x64 tile/CTA, 4x4 outputs/thread, accumulators packed over
// j (4x2 f32x2). Inner loop processes a FUSED (MUFU-h, Newton-h) pair so both
// the MUFU and FMA pipes have ready work in every scheduling window.
// u staged pre-duplicated as (u,u) u64 in smem (no pack movs in the hot loop).
// MUFU h:   t = tanh.approx(u+v);           acc += a*t
// Newton h: tanh(u+v) = (tu+tv)/(1+tu*tv);  rcp = bit-seed + fused cubic
//           correction z*(1+e+e^2) on the FMA pipe (a pre-negated).
// ---------------------------------------------------------------------------
__global__ __launch_bounds__(256, 4) void coattn_kernel(
    const float* __restrict__ a_vec, float* __restrict__ out)
{
    __shared__ u64   s_u2[64][34];     // [i-row][h] = (u,u), padded (16B-aligned)
    __shared__ float s_v[HH][68];      // [h][j-col] transposed, padded
    __shared__ u64   s_a2[HH];         // (a_h, a_h), negated for Newton h

    int b  = blockIdx.z;
    int i0 = blockIdx.y * 64;
    int j0 = blockIdx.x * 64;
    int tid = threadIdx.x;

    const float* ca = g_ca + (b * NN + i0) * HH;
    const float* dv = g_dv + (b * NN + j0) * HH;

#pragma unroll
    for (int k = 0; k < 2; k++) {
        int idx = tid + k * 256;       // 0..511
        int row = idx >> 3, g = idx & 7;
        float4 uu = *reinterpret_cast<const float4*>(ca + row * HH + 4 * g);
        s_u2[row][4 * g + 0] = pack2(uu.x, uu.x);
        s_u2[row][4 * g + 1] = pack2(uu.y, uu.y);
        s_u2[row][4 * g + 2] = pack2(uu.z, uu.z);
        s_u2[row][4 * g + 3] = pack2(uu.w, uu.w);
        float4 vv = *reinterpret_cast<const float4*>(dv + row * HH + 4 * g);
        s_v[4 * g + 0][row] = vv.x;
        s_v[4 * g + 1][row] = vv.y;
        s_v[4 * g + 2][row] = vv.z;
        s_v[4 * g + 3][row] = vv.w;
    }
    if (tid < HH) {
        float av = a_vec[tid];
        if (IS_NEWTON(tid)) av = -av;  // folds r = -s*z sign on Newton path
        s_a2[tid] = pack2(av, av);
    }
    __syncthreads();

    int tx = tid & 15;        // j quad (4 consecutive cols -> float4 store)
    int ty = tid >> 4;        // i quad

    u64 acc[4][2];
#pragma unroll
    for (int r = 0; r < 4; r++) { acc[r][0] = 0ULL; acc[r][1] = 0ULL; }

    // 15 fused (MUFU even-h, Newton odd-h) pairs.
#pragma unroll
    for (int k = 0; k < 15; k++) {
        const int hm = 2 * k, hn = 2 * k + 1;
        float4 vm4 = *reinterpret_cast<float4*>(&s_v[hm][tx * 4]);
        float4 vn4 = *reinterpret_cast<float4*>(&s_v[hn][tx * 4]);
        u64 vm[2] = { pack2(vm4.x, vm4.y), pack2(vm4.z, vm4.w) };
        u64 vn[2] = { pack2(vn4.x, vn4.y), pack2(vn4.z, vn4.w) };
        u64 a2m = s_a2[hm], a2n = s_a2[hn];

#pragma unroll
        for (int r = 0; r < 4; r++) {
            u64 um = s_u2[ty * 4 + r][hm];   // (u,u) broadcast LDS.64
            u64 un = s_u2[ty * 4 + r][hn];
#pragma unroll
            for (int cp = 0; cp < 2; cp++) {
                // --- MUFU stream (h = hm) ---
                u64 sm = f2_add(um, vm[cp]);
                float sl, sh; unpack2(sm, sl, sh);
                // --- Newton stream (h = hn) ---
                u64 sn = f2_add(un, vn[cp]);
                u64 dn = f2_fma(un, vn[cp], ONE2);       // d = 1+tu*tv
                float dl, dh; unpack2(dn, dl, dh);
                u64 z = pack2(rcp_seed(dl), rcp_seed(dh));
                u64 tm = pack2(tanh_a(sl), tanh_a(sh));  // 2x MUFU
                u64 e = f2_fma(dn, z, ONE2);             // e = 1 + d*z
                u64 p = f2_fma(e, e, e);                 // e + e^2
                z     = f2_fma(z, p, z);                 // -1/d, err ~ e^3
                acc[r][cp] = f2_fma(a2m, tm, acc[r][cp]);
                u64 pn = f2_mul(sn, z);                  // -s/d
                acc[r][cp] = f2_fma(a2n, pn, acc[r][cp]);// a2n pre-negated
            }
        }
    }

    // Lone MUFU h's: 30, 31.
#pragma unroll
    for (int h = 30; h < 32; h++) {
        float4 vv = *reinterpret_cast<float4*>(&s_v[h][tx * 4]);
        u64 v2[2] = { pack2(vv.x, vv.y), pack2(vv.z, vv.w) };
        u64 a2 = s_a2[h];
#pragma unroll
        for (int r = 0; r < 4; r++) {
            u64 up = s_u2[ty * 4 + r][h];
#pragma unroll
            for (int cp = 0; cp < 2; cp++) {
                u64 s2 = f2_add(up, v2[cp]);
                float lo, hi; unpack2(s2, lo, hi);
                u64 t2 = pack2(tanh_a(lo), tanh_a(hi));
                acc[r][cp] = f2_fma(a2, t2, acc[r][cp]);
            }
        }
    }

    // Stores straight from the j-packed accumulators.
#pragma unroll
    for (int r = 0; r < 4; r++) {
        float o0, o1, o2, o3;
        unpack2(acc[r][0], o0, o1);
        unpack2(acc[r][1], o2, o3);
        int i = i0 + ty * 4 + r;
        *reinterpret_cast<float4*>(out + ((size_t)b * NN + i) * NN + j0 + tx * 4) =
            make_float4(o0, o1, o2, o3);
    }
}

extern "C" void kernel_launch(void* const* d_in, const int* in_sizes, int n_in,
                              void* d_out, int out_size)
{
    const float* cell = (const float*)d_in[0];
    const float* drug = (const float*)d_in[1];
    const float* w_q  = (const float*)d_in[2];
    const float* w_k  = (const float*)d_in[3];
    const float* bias = (const float*)d_in[4];
    const float* a    = (const float*)d_in[5];
    float* out = (float*)d_out;

    proj_kernel<<<(2 * BB * NN) / 4, 128>>>(cell, drug, w_q, w_k, bias);

    dim3 grid(NN / 64, NN / 64, BB);
    coattn_kernel<<<grid, 256>>>(a, out);
}

// round 9
// speedup vs baseline: 1.0419x; 1.0419x over previous
#include <cuda_runtime.h>
#include <cstdint>

#define BB 8
#define NN 1024
#define DD 64
#define HH 32

// Interleaved path assignment: 17 MUFU h's spread evenly among 32.
#define IS_MUFU(h) ((((h) + 1) * 17 >> 5) > ((h) * 17 >> 5))

// Scratch (allocation-free rule -> device globals).
// MUFU h's: raw projection; Newton h's: tanh(projection).
__device__ float g_ca[BB * NN * HH];
__device__ float g_dv[BB * NN * HH];

using u64 = unsigned long long;

__device__ __forceinline__ u64 f2_add(u64 a, u64 b) {
    u64 r; asm("add.rn.f32x2 %0,%1,%2;" : "=l"(r) : "l"(a), "l"(b)); return r;
}
__device__ __forceinline__ u64 f2_mul(u64 a, u64 b) {
    u64 r; asm("mul.rn.f32x2 %0,%1,%2;" : "=l"(r) : "l"(a), "l"(b)); return r;
}
__device__ __forceinline__ u64 f2_fma(u64 a, u64 b, u64 c) {
    u64 r; asm("fma.rn.f32x2 %0,%1,%2,%3;" : "=l"(r) : "l"(a), "l"(b), "l"(c)); return r;
}
__device__ __forceinline__ u64 pack2(float lo, float hi) {
    u64 r; asm("mov.b64 %0,{%1,%2};" : "=l"(r) : "f"(lo), "f"(hi)); return r;
}
__device__ __forceinline__ void unpack2(u64 v, float& lo, float& hi) {
    asm("mov.b64 {%0,%1},%2;" : "=f"(lo), "=f"(hi) : "l"(v));
}
__device__ __forceinline__ float tanh_a(float x) {
    float r; asm("tanh.approx.f32 %0,%1;" : "=f"(r) : "f"(x)); return r;
}

#define ONE2 0x3F8000003F800000ULL

// ---------------------------------------------------------------------------
// Projection (shuffle-free, register-blocked): 256 threads/block, 32 rows per
// block, 8 threads per row, each thread computes 4 consecutive h for one row.
// x rows and W staged in smem; per d-step: 1 broadcast LDS + 1 LDS.128 + 4 FFMA.
// MUFU-h outputs raw, Newton-h outputs tanh'd.
// ---------------------------------------------------------------------------
#define ROWS_PB 32
__global__ __launch_bounds__(256) void proj_kernel(
    const float* __restrict__ cell, const float* __restrict__ drug,
    const float* __restrict__ w_q, const float* __restrict__ w_k,
    const float* __restrict__ bias)
{
    __shared__ float s_x[ROWS_PB][68];   // padded rows
    __shared__ float s_w[DD][HH];        // 8 KB, same layout as global W

    int tid = threadIdx.x;
    int blk = blockIdx.x;                            // 0..511
    const int blocks_per_side = (BB * NN) / ROWS_PB; // 256
    bool is_drug = blk >= blocks_per_side;
    int row0 = (is_drug ? blk - blocks_per_side : blk) * ROWS_PB;
    const float* src = (is_drug ? drug : cell) + (size_t)row0 * DD;
    const float* W   = is_drug ? w_q : w_k;

    // Stage x: 32 rows x 64 floats = 512 float4 (coalesced), 2 per thread.
#pragma unroll
    for (int k = 0; k < 2; k++) {
        int idx = tid + k * 256;         // float4 index 0..511
        int row = idx >> 4, d4 = idx & 15;
        float4 v = *reinterpret_cast<const float4*>(src + row * DD + d4 * 4);
        *reinterpret_cast<float4*>(&s_x[row][d4 * 4]) = v;
    }
    // Stage W: 2048 floats = 512 float4, 2 per thread.
#pragma unroll
    for (int k = 0; k < 2; k++) {
        int idx = tid + k * 256;
        *reinterpret_cast<float4*>(reinterpret_cast<float*>(s_w) + idx * 4) =
            *reinterpret_cast<const float4*>(W + idx * 4);
    }
    __syncthreads();

    int hq  = tid & 7;       // h quad: h = hq*4 + c, covers h 0..31
    int row = tid >> 3;      // 0..31

    float a0 = 0.f, a1 = 0.f, a2 = 0.f, a3 = 0.f;
#pragma unroll
    for (int d = 0; d < DD; d++) {
        float x = s_x[row][d];
        float4 w4 = *reinterpret_cast<float4*>(&s_w[d][hq * 4]);
        a0 = fmaf(x, w4.x, a0);
        a1 = fmaf(x, w4.y, a1);
        a2 = fmaf(x, w4.z, a2);
        a3 = fmaf(x, w4.w, a3);
    }

    int h0 = hq * 4;
    float o[4] = {a0, a1, a2, a3};
    if (is_drug) {
        float4 b4 = *reinterpret_cast<const float4*>(bias + h0);
        o[0] += b4.x; o[1] += b4.y; o[2] += b4.z; o[3] += b4.w;
    }
#pragma unroll
    for (int c = 0; c < 4; c++)
        if (!IS_MUFU(h0 + c)) o[c] = tanh_a(o[c]);   // Newton lanes store tanh'd

    float* dst = (is_drug ? g_dv : g_ca) + (size_t)(row0 + row) * HH + h0;
    *reinterpret_cast<float4*>(dst) = make_float4(o[0], o[1], o[2], o[3]);
}

// ---------------------------------------------------------------------------
// Co-attention (R6 best variant): 64x64 tile/CTA, 4x4 outputs/thread,
// accumulators packed over j (4x2 f32x2). h in groups of 2, MUFU/Newton h's
// interleaved so both pipes stay loaded.
// MUFU h:   e = u+v; tanh.approx on MUFU; acc += a*t
// Newton h: tanh(u+v) = (tu+tv)/(1+tu*tv); reciprocal = bit-seed + one fused
//           cubic correction z*(1+e+e^2) on the FMA pipe (err ~ e0^3).
// ---------------------------------------------------------------------------
__global__ __launch_bounds__(256, 5) void coattn_kernel(
    const float* __restrict__ a_vec, float* __restrict__ out)
{
    __shared__ float s_u[64][36];      // [i-row][h], padded (16B-aligned rows)
    __shared__ float s_v[HH][68];      // [h][j-col] transposed, padded
    __shared__ u64   s_a2[HH];         // (a_h, a_h), negated for Newton h

    int b  = blockIdx.z;
    int i0 = blockIdx.y * 64;
    int j0 = blockIdx.x * 64;
    int tid = threadIdx.x;

    const float* ca = g_ca + (b * NN + i0) * HH;
    const float* dv = g_dv + (b * NN + j0) * HH;

#pragma unroll
    for (int k = 0; k < 2; k++) {
        int idx = tid + k * 256;       // 0..511
        int row = idx >> 3, g = idx & 7;
        float4 uu = *reinterpret_cast<const float4*>(ca + row * HH + 4 * g);
        *reinterpret_cast<float4*>(&s_u[row][4 * g]) = uu;
        float4 vv = *reinterpret_cast<const float4*>(dv + row * HH + 4 * g);
        s_v[4 * g + 0][row] = vv.x;
        s_v[4 * g + 1][row] = vv.y;
        s_v[4 * g + 2][row] = vv.z;
        s_v[4 * g + 3][row] = vv.w;
    }
    if (tid < HH) {
        float av = a_vec[tid];
        if (!IS_MUFU(tid)) av = -av;   // folds r = -s*z sign on Newton path
        s_a2[tid] = pack2(av, av);
    }
    __syncthreads();

    int tx = tid & 15;        // j quad (4 consecutive cols -> float4 store)
    int ty = tid >> 4;        // i quad

    u64 acc[4][2];
#pragma unroll
    for (int r = 0; r < 4; r++) { acc[r][0] = 0ULL; acc[r][1] = 0ULL; }

#pragma unroll
    for (int g = 0; g < 16; g++) {                // h-groups of 2 (mixed paths)
        float2 u2r[4];
#pragma unroll
        for (int r = 0; r < 4; r++)
            u2r[r] = *reinterpret_cast<float2*>(&s_u[ty * 4 + r][2 * g]);

#pragma unroll
        for (int k = 0; k < 2; k++) {
            const int h = 2 * g + k;              // compile-time
            float4 vv = *reinterpret_cast<float4*>(&s_v[h][tx * 4]);
            u64 v2[2] = { pack2(vv.x, vv.y), pack2(vv.z, vv.w) };
            u64 a2 = s_a2[h];

#pragma unroll
            for (int r = 0; r < 4; r++) {
                float us = k ? u2r[r].y : u2r[r].x;
                u64 up = pack2(us, us);
#pragma unroll
                for (int cp = 0; cp < 2; cp++) {
                    u64 s2 = f2_add(up, v2[cp]);
                    if (IS_MUFU(h)) {
                        float lo, hi; unpack2(s2, lo, hi);
                        u64 t2 = pack2(tanh_a(lo), tanh_a(hi));
                        acc[r][cp] = f2_fma(a2, t2, acc[r][cp]);
                    } else {
                        u64 d2 = f2_fma(up, v2[cp], ONE2);          // d = 1+tu*tv
                        float dl, dh; unpack2(d2, dl, dh);
                        u64 z = pack2(                               // z0 ~ -1/d seed
                            __uint_as_float(0xFEF311C3u - __float_as_uint(dl)),
                            __uint_as_float(0xFEF311C3u - __float_as_uint(dh)));
                        u64 e = f2_fma(d2, z, ONE2);                 // e = 1 + d*z
                        u64 p = f2_fma(e, e, e);                     // e + e^2
                        z     = f2_fma(z, p, z);                     // z(1+e+e^2): -1/d, err e^3
                        u64 pp = f2_mul(s2, z);                      // -s/d
                        acc[r][cp] = f2_fma(a2, pp, acc[r][cp]);     // a2 pre-negated
                    }
                }
            }
        }
    }

    // Stores come straight from the j-packed accumulators.
#pragma unroll
    for (int r = 0; r < 4; r++) {
        float o0, o1, o2, o3;
        unpack2(acc[r][0], o0, o1);
        unpack2(acc[r][1], o2, o3);
        int i = i0 + ty * 4 + r;
        *reinterpret_cast<float4*>(out + ((size_t)b * NN + i) * NN + j0 + tx * 4) =
            make_float4(o0, o1, o2, o3);
    }
}

extern "C" void kernel_launch(void* const* d_in, const int* in_sizes, int n_in,
                              void* d_out, int out_size)
{
    const float* cell = (const float*)d_in[0];
    const float* drug = (const float*)d_in[1];
    const float* w_q  = (const float*)d_in[2];
    const float* w_k  = (const float*)d_in[3];
    const float* bias = (const float*)d_in[4];
    const float* a    = (const float*)d_in[5];
    float* out = (float*)d_out;

    proj_kernel<<<2 * (BB * NN) / ROWS_PB, 256>>>(cell, drug, w_q, w_k, bias);

    dim3 grid(NN / 64, NN / 64, BB);
    coattn_kernel<<<grid, 256>>>(a, out);
}